// round 1
// baseline (speedup 1.0000x reference)
#include <cuda_runtime.h>
#include <math.h>

#define B_ 32
#define S_ 512
#define E_ 300
#define F_ 100
#define T_ 50

// Scratch (no allocations allowed): emissions [B,S,T] and per-batch partials.
__device__ float g_em[B_ * S_ * T_];
__device__ float g_part[B_];

// ---------------------------------------------------------------------------
// Kernel 1: embedding gather + conv1d(K=3, pad=1) + bias + ReLU + FC -> emissions
// One block handles 32 consecutive positions of one batch row.
// grid = (16, 32), block = 256.
// ---------------------------------------------------------------------------
__global__ __launch_bounds__(256) void k_emissions(
    const int* __restrict__ x,
    const float* __restrict__ emb,
    const float* __restrict__ conv_w,   // [F,E,K] = f*900 + e*3 + k
    const float* __restrict__ conv_b,
    const float* __restrict__ fc_w,     // [T,F]
    const float* __restrict__ fc_b)
{
    // emb tile: 34 rows x 300 floats, padded row stride 301 (conflict-free for
    // stride-4-row lane access: 4*301 mod 32 = 20, gcd(20,32)=4 -> distinct for st 0..7).
    __shared__ float sbuf[34 * 301];    // 40,936 B; later reused: feat[32*100] @0, fc_w[50*101] @3200
    __shared__ int   sx[34];

    const int tid = threadIdx.x;
    const int b   = blockIdx.y;
    const int s0  = blockIdx.x * 32;

    if (tid < 34) {
        int sg = s0 - 1 + tid;                    // conv input index s+k-1, k in [0,3)
        sx[tid] = (sg >= 0 && sg < S_) ? x[b * S_ + sg] : -1;
    }
    __syncthreads();

    for (int idx = tid; idx < 34 * E_; idx += 256) {
        int r = idx / E_, e = idx - r * E_;
        int v = sx[r];
        sbuf[r * 301 + e] = (v >= 0) ? __ldg(&emb[v * E_ + e]) : 0.f;
    }
    __syncthreads();

    // Conv: 200 active threads, each computes a 4(s) x 4(f) accumulator tile.
    float acc[4][4];
    int ft = 0, sb = 0;
    if (tid < 200) {
        ft = tid >> 3;            // 0..24  -> f0 = 4*ft
        sb = (tid & 7) * 4;       // 0..28  -> s tile base
        #pragma unroll
        for (int i = 0; i < 4; i++)
            #pragma unroll
            for (int j = 0; j < 4; j++) acc[i][j] = 0.f;

        const float* wbase = conv_w + ft * 4 * (E_ * 3);
        for (int e = 0; e < E_; e++) {
            float ev[6];
            #pragma unroll
            for (int r = 0; r < 6; r++) ev[r] = sbuf[(sb + r) * 301 + e];
            #pragma unroll
            for (int fj = 0; fj < 4; fj++) {
                const float* wp = wbase + fj * (E_ * 3) + e * 3;
                float w0 = __ldg(wp + 0), w1 = __ldg(wp + 1), w2 = __ldg(wp + 2);
                #pragma unroll
                for (int si = 0; si < 4; si++)
                    acc[si][fj] += ev[si] * w0 + ev[si + 1] * w1 + ev[si + 2] * w2;
            }
        }
    }
    __syncthreads();   // all emb reads done; sbuf can be reused

    if (tid < 200) {
        #pragma unroll
        for (int fj = 0; fj < 4; fj++) {
            float bb = __ldg(&conv_b[ft * 4 + fj]);
            #pragma unroll
            for (int si = 0; si < 4; si++)
                sbuf[(sb + si) * F_ + ft * 4 + fj] = fmaxf(acc[si][fj] + bb, 0.f);
        }
    }
    // Stage fc_w transposed-padded at word offset 3200 (stride 101: conflict-free).
    for (int idx = tid; idx < T_ * F_; idx += 256) {
        int t = idx / F_, f = idx - t * F_;
        sbuf[3200 + t * 101 + f] = __ldg(&fc_w[idx]);
    }
    __syncthreads();

    // FC: em[s][t] = feat[s][:] . fc_w[t][:] + fc_b[t]
    for (int idx = tid; idx < 32 * T_; idx += 256) {
        int s = idx / T_, t = idx - s * T_;
        float d = __ldg(&fc_b[t]);
        const float* fv = &sbuf[s * F_];
        const float* fw = &sbuf[3200 + t * 101];
        #pragma unroll 10
        for (int f = 0; f < F_; f++) d += fv[f] * fw[f];
        g_em[(b * S_ + (s0 + s)) * T_ + t] = d;
    }
}

// ---------------------------------------------------------------------------
// Kernel 2: CRF forward algorithm + gold-path score. One block per batch item.
// alpha kept in registers (thread j holds alpha_j). Per step:
//   m = max_i alpha_i ; p_i = exp(alpha_i - m) ; alpha_j = m + log(p . E[:,j]) + em_j
// where E = exp(trans) precomputed in smem (valid: trans bounded in [-0.1,0.1]).
// grid = 32, block = 64.
// ---------------------------------------------------------------------------
__global__ __launch_bounds__(64) void k_crf(
    const int* __restrict__ tags,
    const float* __restrict__ start_trans,
    const float* __restrict__ end_trans,
    const float* __restrict__ trans)
{
    __shared__ float sE[T_ * 51];   // exp(trans), padded stride 51
    __shared__ float p[T_];
    __shared__ float red[2];
    __shared__ float s_num;

    const int tid  = threadIdx.x;
    const int lane = tid & 31, wid = tid >> 5;
    const int b    = blockIdx.x;

    for (int idx = tid; idx < T_ * T_; idx += 64) {
        int i = idx / T_, j = idx - i * T_;
        sE[i * 51 + j] = expf(__ldg(&trans[idx]));
    }

    // --- numerator: gold path score ---
    const int* tg = tags + b * S_;
    float local = 0.f;
    for (int s = tid; s < S_; s += 64) {
        int t = tg[s];
        local += g_em[(b * S_ + s) * T_ + t];
        if (s < S_ - 1) local += __ldg(&trans[t * T_ + tg[s + 1]]);
    }
    #pragma unroll
    for (int off = 16; off; off >>= 1) local += __shfl_xor_sync(0xffffffffu, local, off);
    __syncthreads();                       // also orders sE staging before use
    if (lane == 0) red[wid] = local;
    __syncthreads();
    if (tid == 0) s_num = red[0] + red[1] + start_trans[tg[0]] + end_trans[tg[S_ - 1]];
    __syncthreads();

    // --- forward scan ---
    float a = -3.0e38f;
    if (tid < T_) a = __ldg(&start_trans[tid]) + g_em[(b * S_ + 0) * T_ + tid];
    float em_c = (tid < T_) ? g_em[(b * S_ + 1) * T_ + tid] : 0.f;

    for (int s = 1; s < S_; s++) {
        float av = (tid < T_) ? a : -3.0e38f;
        #pragma unroll
        for (int off = 16; off; off >>= 1)
            av = fmaxf(av, __shfl_xor_sync(0xffffffffu, av, off));
        if (lane == 0) red[wid] = av;
        __syncthreads();                   // bar A
        float m = fmaxf(red[0], red[1]);
        if (tid < T_) p[tid] = expf(a - m);
        // prefetch next step's emission while p settles
        float em_n = (tid < T_ && s + 1 < S_) ? g_em[(b * S_ + s + 1) * T_ + tid] : 0.f;
        __syncthreads();                   // bar B
        if (tid < T_) {
            float d0 = 0.f, d1 = 0.f;
            #pragma unroll
            for (int i = 0; i < T_; i += 2) {
                d0 += p[i]     * sE[i * 51 + tid];
                d1 += p[i + 1] * sE[(i + 1) * 51 + tid];
            }
            a = m + logf(d0 + d1) + em_c;
        }
        em_c = em_n;
        // no trailing bar needed: next iter's p/red writes are after bar A/B there
    }

    // --- log_z = logsumexp_j(alpha_j + end_trans_j) ---
    float av = (tid < T_) ? a + __ldg(&end_trans[tid]) : -3.0e38f;
    float mv = av;
    #pragma unroll
    for (int off = 16; off; off >>= 1)
        mv = fmaxf(mv, __shfl_xor_sync(0xffffffffu, mv, off));
    __syncthreads();
    if (lane == 0) red[wid] = mv;
    __syncthreads();
    float m = fmaxf(red[0], red[1]);
    float ex = (tid < T_) ? expf(av - m) : 0.f;
    #pragma unroll
    for (int off = 16; off; off >>= 1) ex += __shfl_xor_sync(0xffffffffu, ex, off);
    __syncthreads();
    if (lane == 0) red[wid] = ex;
    __syncthreads();
    if (tid == 0) g_part[b] = (m + logf(red[0] + red[1])) - s_num;
}

// Deterministic final reduction (avoids float atomics).
__global__ void k_final(float* out)
{
    float v = g_part[threadIdx.x];
    #pragma unroll
    for (int off = 16; off; off >>= 1) v += __shfl_xor_sync(0xffffffffu, v, off);
    if (threadIdx.x == 0) out[0] = v;
}

extern "C" void kernel_launch(void* const* d_in, const int* in_sizes, int n_in,
                              void* d_out, int out_size)
{
    const int*   x           = (const int*)  d_in[0];
    const int*   tags        = (const int*)  d_in[1];
    const float* emb         = (const float*)d_in[2];
    const float* conv_w      = (const float*)d_in[3];
    const float* conv_b      = (const float*)d_in[4];
    const float* fc_w        = (const float*)d_in[5];
    const float* fc_b        = (const float*)d_in[6];
    const float* start_trans = (const float*)d_in[7];
    const float* end_trans   = (const float*)d_in[8];
    const float* trans       = (const float*)d_in[9];
    float* out = (float*)d_out;

    dim3 g1(S_ / 32, B_);
    k_emissions<<<g1, 256>>>(x, emb, conv_w, conv_b, fc_w, fc_b);
    k_crf<<<B_, 64>>>(tags, start_trans, end_trans, trans);
    k_final<<<1, 32>>>(out);
}

// round 2
// speedup vs baseline: 1.5641x; 1.5641x over previous
#include <cuda_runtime.h>
#include <math.h>
#include <stdint.h>

#define B_ 32
#define S_ 512
#define E_ 300
#define F_ 100
#define T_ 50
#define EC 30   // e-chunk for emissions smem staging

// Scratch (no allocations allowed)
__device__ float g_em[B_ * S_ * T_];       // emissions [B,S,T]
__device__ float g_part[B_];
__device__ float g_wt[E_ * F_ * 3];        // conv_w repacked: [e][k][f]

// ---- packed fp32x2 helpers (sm_103a) ----
#define PACK2(d, lo, hi) \
    asm("mov.b64 %0, {%1, %2};" : "=l"(d) : "r"(__float_as_uint(lo)), "r"(__float_as_uint(hi)))
#define FMA2(d, a, b) \
    asm("fma.rn.f32x2 %0, %1, %2, %0;" : "+l"(d) : "l"(a), "l"(b))
#define UNPACK2(lo, hi, v) do { unsigned _l, _h; \
    asm("mov.b64 {%0, %1}, %2;" : "=r"(_l), "=r"(_h) : "l"(v)); \
    lo = __uint_as_float(_l); hi = __uint_as_float(_h); } while (0)

// ---------------------------------------------------------------------------
// Kernel 0: repack conv_w [F][E][K] -> g_wt [E][K][F]  (f contiguous -> float4)
// ---------------------------------------------------------------------------
__global__ void k_wt(const float* __restrict__ cw)
{
    int i = blockIdx.x * 256 + threadIdx.x;
    if (i < F_ * E_ * 3) {
        int f = i / (E_ * 3), r = i % (E_ * 3);
        int e = r / 3, k = r % 3;
        g_wt[e * (3 * F_) + k * F_ + f] = cw[i];
    }
}

// ---------------------------------------------------------------------------
// Kernel 1: emb gather + conv1d(K=3,pad=1) + bias + ReLU + FC -> emissions
// Block: 256 threads, covers 64 s-positions of one batch row. grid = (8, 32).
// Compute threads (200): ft = tid>>3 (0..24, 4 f each), sg = tid&7 (8 s each).
// Inner loop uses packed f32x2 FMAs: 48 FMA2 = 96 FMA per e per thread.
// ---------------------------------------------------------------------------
__global__ __launch_bounds__(256, 2) void k_emissions(
    const int* __restrict__ x,
    const float* __restrict__ emb,
    const float* __restrict__ conv_b,
    const float* __restrict__ fc_w,     // [T,F]
    const float* __restrict__ fc_b)
{
    // sbuf: phase1 sT[EC][68] (2040 floats) | phase2 feat[64][100] (6400) + fcwT[100][52] (5200)
    __shared__ __align__(16) float sbuf[11600];   // 46.4 KB
    __shared__ int sx[66];

    const int tid = threadIdx.x;
    const int b   = blockIdx.y;
    const int s0  = blockIdx.x * 64;

    float* sT   = sbuf;
    float* feat = sbuf;
    float* fcwT = sbuf + 6400;

    if (tid < 66) {
        int sg_ = s0 - 1 + tid;
        sx[tid] = (sg_ >= 0 && sg_ < S_) ? x[b * S_ + sg_] : -1;
    }
    // stage fc_w transposed [f][t], stride 52 (region disjoint from sT)
    for (int idx = tid; idx < T_ * F_; idx += 256) {
        int t = idx / F_, f = idx - t * F_;       // coalesced read
        fcwT[f * 52 + t] = __ldg(&fc_w[idx]);
    }

    const int ft = tid >> 3;       // f-group (valid < 25)
    const int sg = tid & 7;        // s-group
    const bool act = (tid < 200);

    uint64_t acc[8][2];
    #pragma unroll
    for (int i = 0; i < 8; i++) { acc[i][0] = 0ull; acc[i][1] = 0ull; }

    for (int ec0 = 0; ec0 < E_; ec0 += EC) {
        __syncthreads();    // previous chunk's reads complete (also covers init stages)
        for (int idx = tid; idx < EC * 66; idx += 256) {
            int r = idx / EC, el = idx - r * EC;   // consecutive tid -> consecutive e (coalesced)
            int v = sx[r];
            sT[el * 68 + r] = (v >= 0) ? __ldg(&emb[v * E_ + ec0 + el]) : 0.f;
        }
        __syncthreads();
        if (act) {
            #pragma unroll 5
            for (int el = 0; el < EC; el++) {
                const float* row = sT + el * 68 + sg * 8;
                float4 v0 = *(const float4*)(row);
                float4 v1 = *(const float4*)(row + 4);
                float2 v2 = *(const float2*)(row + 8);
                float ev[10] = {v0.x, v0.y, v0.z, v0.w, v1.x, v1.y, v1.z, v1.w, v2.x, v2.y};
                uint64_t ev2[10];
                #pragma unroll
                for (int r2 = 0; r2 < 10; r2++) PACK2(ev2[r2], ev[r2], ev[r2]);

                const float* wb = g_wt + (ec0 + el) * (3 * F_) + ft * 4;
                float4 w0 = __ldg((const float4*)(wb));            // k=0, f0..f3
                float4 w1 = __ldg((const float4*)(wb + F_));       // k=1
                float4 w2 = __ldg((const float4*)(wb + 2 * F_));   // k=2
                uint64_t wk[3][2];
                PACK2(wk[0][0], w0.x, w0.y); PACK2(wk[0][1], w0.z, w0.w);
                PACK2(wk[1][0], w1.x, w1.y); PACK2(wk[1][1], w1.z, w1.w);
                PACK2(wk[2][0], w2.x, w2.y); PACK2(wk[2][1], w2.z, w2.w);

                #pragma unroll
                for (int si = 0; si < 8; si++) {
                    #pragma unroll
                    for (int fp = 0; fp < 2; fp++) {
                        FMA2(acc[si][fp], ev2[si],     wk[0][fp]);
                        FMA2(acc[si][fp], ev2[si + 1], wk[1][fp]);
                        FMA2(acc[si][fp], ev2[si + 2], wk[2][fp]);
                    }
                }
            }
        }
    }
    __syncthreads();   // conv reads of sT done -> safe to overwrite with feat

    if (act) {
        float b0 = __ldg(&conv_b[ft * 4 + 0]);
        float b1 = __ldg(&conv_b[ft * 4 + 1]);
        float b2 = __ldg(&conv_b[ft * 4 + 2]);
        float b3 = __ldg(&conv_b[ft * 4 + 3]);
        #pragma unroll
        for (int si = 0; si < 8; si++) {
            float x0, x1, x2, x3;
            UNPACK2(x0, x1, acc[si][0]);
            UNPACK2(x2, x3, acc[si][1]);
            float* fr = feat + (sg * 8 + si) * F_ + ft * 4;
            fr[0] = fmaxf(x0 + b0, 0.f);
            fr[1] = fmaxf(x1 + b1, 0.f);
            fr[2] = fmaxf(x2 + b2, 0.f);
            fr[3] = fmaxf(x3 + b3, 0.f);
        }
    }
    __syncthreads();

    // FC: em[s][t] = feat[s][:] . fc_w[t][:] + fc_b[t]
    for (int idx = tid; idx < 64 * T_; idx += 256) {
        int s = idx / T_, t = idx - s * T_;
        float d = __ldg(&fc_b[t]);
        const float* fv = feat + s * F_;
        const float* fw = fcwT + t;
        #pragma unroll 10
        for (int f = 0; f < F_; f++) d += fv[f] * fw[f * 52];
        g_em[(b * S_ + (s0 + s)) * T_ + t] = d;
    }
}

// ---------------------------------------------------------------------------
// Kernel 2: CRF in linear (probability) domain. One block per batch, 64 thr.
// Thread j (<50) owns alpha_j (prob) and E column j in 25 packed f32x2 regs.
// Step: p <- (p . E) * exp(em_t); renormalize by max every 8 steps.
// ---------------------------------------------------------------------------
__global__ __launch_bounds__(64) void k_crf(
    const int* __restrict__ tags,
    const float* __restrict__ start_trans,
    const float* __restrict__ end_trans,
    const float* __restrict__ trans)
{
    __shared__ __align__(16) float p[52];
    __shared__ float red[2];
    __shared__ float s_num;

    const int tid  = threadIdx.x;
    const int lane = tid & 31, wid = tid >> 5;
    const int b    = blockIdx.x;
    const int base = b * S_;

    // E columns in registers: Ecol2[i] = (exp(trans[2i][tid]), exp(trans[2i+1][tid]))
    uint64_t Ecol2[25];
    if (tid < T_) {
        #pragma unroll
        for (int i = 0; i < 25; i++) {
            float e0 = __expf(__ldg(&trans[(2 * i) * T_ + tid]));
            float e1 = __expf(__ldg(&trans[(2 * i + 1) * T_ + tid]));
            PACK2(Ecol2[i], e0, e1);
        }
    }

    // --- numerator: gold path score ---
    const int* tg = tags + base;
    float local = 0.f;
    for (int s = tid; s < S_; s += 64) {
        int t = tg[s];
        local += g_em[(base + s) * T_ + t];
        if (s < S_ - 1) local += __ldg(&trans[t * T_ + tg[s + 1]]);
    }
    #pragma unroll
    for (int off_ = 16; off_; off_ >>= 1) local += __shfl_xor_sync(0xffffffffu, local, off_);
    if (lane == 0) red[wid] = local;
    __syncthreads();
    if (tid == 0) s_num = red[0] + red[1] + start_trans[tg[0]] + end_trans[tg[S_ - 1]];

    // --- init alpha (log) then convert to linear with offset ---
    float alog = (tid < T_) ? (__ldg(&start_trans[tid]) + g_em[base * T_ + tid]) : -3.0e38f;
    float rv = alog;
    #pragma unroll
    for (int off_ = 16; off_; off_ >>= 1) rv = fmaxf(rv, __shfl_xor_sync(0xffffffffu, rv, off_));
    __syncthreads();                 // red free for reuse (s_num consumed it)
    if (lane == 0) red[wid] = rv;
    __syncthreads();
    float m0  = fmaxf(red[0], red[1]);
    float off = m0;
    float a   = (tid < T_) ? __expf(alog - m0) : 0.f;
    float em_c = (tid < T_) ? g_em[(base + 1) * T_ + tid] : 0.f;

    // --- forward scan, linear domain ---
    for (int s = 1; s < S_; s++) {
        float em_n = (tid < T_ && s + 1 < S_) ? __ldg(&g_em[(base + s + 1) * T_ + tid]) : 0.f;
        float eem = __expf(em_c);
        if (tid < T_) p[tid] = a;
        __syncthreads();             // p published
        float anew = 0.f;
        if (tid < T_) {
            uint64_t d0 = 0ull, d1 = 0ull;
            const uint64_t* p2 = (const uint64_t*)p;
            #pragma unroll
            for (int i = 0; i < 25; i++) {
                uint64_t pv = p2[i];
                if (i & 1) { FMA2(d1, pv, Ecol2[i]); } else { FMA2(d0, pv, Ecol2[i]); }
            }
            float l0, h0, l1, h1;
            UNPACK2(l0, h0, d0);
            UNPACK2(l1, h1, d1);
            anew = ((l0 + h0) + (l1 + h1)) * eem;
        }
        bool rn = ((s & 7) == 0);
        if (rn) {
            float mv = (tid < T_) ? anew : 0.f;
            #pragma unroll
            for (int off_ = 16; off_; off_ >>= 1)
                mv = fmaxf(mv, __shfl_xor_sync(0xffffffffu, mv, off_));
            if (lane == 0) red[wid] = mv;
        }
        __syncthreads();             // p reads done + red published
        if (rn) {
            float m = fmaxf(red[0], red[1]);
            anew *= (1.0f / m);
            off += __logf(m);
        }
        a = anew;
        em_c = em_n;
    }

    // --- log_z = off + log(sum_j a_j * exp(end_trans_j)) ---
    float av = (tid < T_) ? a * __expf(__ldg(&end_trans[tid])) : 0.f;
    #pragma unroll
    for (int off_ = 16; off_; off_ >>= 1) av += __shfl_xor_sync(0xffffffffu, av, off_);
    if (lane == 0) red[wid] = av;
    __syncthreads();
    if (tid == 0) {
        float log_z = off + logf(red[0] + red[1]);
        g_part[b] = log_z - s_num;
    }
}

// Deterministic final reduction.
__global__ void k_final(float* out)
{
    float v = g_part[threadIdx.x];
    #pragma unroll
    for (int off_ = 16; off_; off_ >>= 1) v += __shfl_xor_sync(0xffffffffu, v, off_);
    if (threadIdx.x == 0) out[0] = v;
}

extern "C" void kernel_launch(void* const* d_in, const int* in_sizes, int n_in,
                              void* d_out, int out_size)
{
    const int*   x           = (const int*)  d_in[0];
    const int*   tags        = (const int*)  d_in[1];
    const float* emb         = (const float*)d_in[2];
    const float* conv_w      = (const float*)d_in[3];
    const float* conv_b      = (const float*)d_in[4];
    const float* fc_w        = (const float*)d_in[5];
    const float* fc_b        = (const float*)d_in[6];
    const float* start_trans = (const float*)d_in[7];
    const float* end_trans   = (const float*)d_in[8];
    const float* trans       = (const float*)d_in[9];
    float* out = (float*)d_out;

    k_wt<<<(F_ * E_ * 3 + 255) / 256, 256>>>(conv_w);
    k_emissions<<<dim3(S_ / 64, B_), 256>>>(x, emb, conv_b, fc_w, fc_b);
    k_crf<<<B_, 64>>>(tags, start_trans, end_trans, trans);
    k_final<<<1, 32>>>(out);
}

// round 3
// speedup vs baseline: 1.7894x; 1.1440x over previous
#include <cuda_runtime.h>
#include <math.h>
#include <stdint.h>

#define B_ 32
#define S_ 512
#define E_ 300
#define F_ 100
#define T_ 50
#define EC 30   // e-chunk for emissions smem staging

// Scratch (no allocations allowed)
__device__ float g_em[B_ * S_ * T_];       // emissions [B,S,T]
__device__ float g_part[B_];
__device__ float g_wt[E_ * F_ * 3];        // conv_w repacked: [e][k][f]
__device__ unsigned g_cnt;                 // last-block counter (self-resetting)

// ---- packed fp32x2 helpers (sm_103a) ----
#define PACK2(d, lo, hi) \
    asm("mov.b64 %0, {%1, %2};" : "=l"(d) : "r"(__float_as_uint(lo)), "r"(__float_as_uint(hi)))
#define FMA2(d, a, b) \
    asm("fma.rn.f32x2 %0, %1, %2, %0;" : "+l"(d) : "l"(a), "l"(b))
#define MUL2(d, a, b) \
    asm("mul.rn.f32x2 %0, %1, %2;" : "=l"(d) : "l"(a), "l"(b))
#define UNPACK2(lo, hi, v) do { unsigned _l, _h; \
    asm("mov.b64 {%0, %1}, %2;" : "=r"(_l), "=r"(_h) : "l"(v)); \
    lo = __uint_as_float(_l); hi = __uint_as_float(_h); } while (0)

// ---------------------------------------------------------------------------
// Kernel 0: repack conv_w [F][E][K] -> g_wt [E][K][F]  (f contiguous -> float4)
// ---------------------------------------------------------------------------
__global__ void k_wt(const float* __restrict__ cw)
{
    int i = blockIdx.x * 256 + threadIdx.x;
    if (i < F_ * E_ * 3) {
        int f = i / (E_ * 3), r = i % (E_ * 3);
        int e = r / 3, k = r % 3;
        g_wt[e * (3 * F_) + k * F_ + f] = cw[i];
    }
}

// ---------------------------------------------------------------------------
// Kernel 1: emb gather + conv1d(K=3,pad=1) + bias + ReLU + FC -> emissions
// Block: 256 threads, 64 s-positions of one batch row. grid = (8, 32).
// ---------------------------------------------------------------------------
__global__ __launch_bounds__(256, 2) void k_emissions(
    const int* __restrict__ x,
    const float* __restrict__ emb,
    const float* __restrict__ conv_b,
    const float* __restrict__ fc_w,     // [T,F]
    const float* __restrict__ fc_b)
{
    __shared__ __align__(16) float sbuf[11600];   // 46.4 KB
    __shared__ int sx[66];

    const int tid = threadIdx.x;
    const int b   = blockIdx.y;
    const int s0  = blockIdx.x * 64;

    float* sT   = sbuf;
    float* feat = sbuf;
    float* fcwT = sbuf + 6400;

    if (tid < 66) {
        int sg_ = s0 - 1 + tid;
        sx[tid] = (sg_ >= 0 && sg_ < S_) ? x[b * S_ + sg_] : -1;
    }
    for (int idx = tid; idx < T_ * F_; idx += 256) {
        int t = idx / F_, f = idx - t * F_;
        fcwT[f * 52 + t] = __ldg(&fc_w[idx]);
    }

    const int ft = tid >> 3;
    const int sg = tid & 7;
    const bool act = (tid < 200);

    uint64_t acc[8][2];
    #pragma unroll
    for (int i = 0; i < 8; i++) { acc[i][0] = 0ull; acc[i][1] = 0ull; }

    for (int ec0 = 0; ec0 < E_; ec0 += EC) {
        __syncthreads();
        for (int idx = tid; idx < EC * 66; idx += 256) {
            int r = idx / EC, el = idx - r * EC;
            int v = sx[r];
            sT[el * 68 + r] = (v >= 0) ? __ldg(&emb[v * E_ + ec0 + el]) : 0.f;
        }
        __syncthreads();
        if (act) {
            #pragma unroll 5
            for (int el = 0; el < EC; el++) {
                const float* row = sT + el * 68 + sg * 8;
                float4 v0 = *(const float4*)(row);
                float4 v1 = *(const float4*)(row + 4);
                float2 v2 = *(const float2*)(row + 8);
                float ev[10] = {v0.x, v0.y, v0.z, v0.w, v1.x, v1.y, v1.z, v1.w, v2.x, v2.y};
                uint64_t ev2[10];
                #pragma unroll
                for (int r2 = 0; r2 < 10; r2++) PACK2(ev2[r2], ev[r2], ev[r2]);

                const float* wb = g_wt + (ec0 + el) * (3 * F_) + ft * 4;
                float4 w0 = __ldg((const float4*)(wb));
                float4 w1 = __ldg((const float4*)(wb + F_));
                float4 w2 = __ldg((const float4*)(wb + 2 * F_));
                uint64_t wk[3][2];
                PACK2(wk[0][0], w0.x, w0.y); PACK2(wk[0][1], w0.z, w0.w);
                PACK2(wk[1][0], w1.x, w1.y); PACK2(wk[1][1], w1.z, w1.w);
                PACK2(wk[2][0], w2.x, w2.y); PACK2(wk[2][1], w2.z, w2.w);

                #pragma unroll
                for (int si = 0; si < 8; si++) {
                    #pragma unroll
                    for (int fp = 0; fp < 2; fp++) {
                        FMA2(acc[si][fp], ev2[si],     wk[0][fp]);
                        FMA2(acc[si][fp], ev2[si + 1], wk[1][fp]);
                        FMA2(acc[si][fp], ev2[si + 2], wk[2][fp]);
                    }
                }
            }
        }
    }
    __syncthreads();

    if (act) {
        float b0 = __ldg(&conv_b[ft * 4 + 0]);
        float b1 = __ldg(&conv_b[ft * 4 + 1]);
        float b2 = __ldg(&conv_b[ft * 4 + 2]);
        float b3 = __ldg(&conv_b[ft * 4 + 3]);
        #pragma unroll
        for (int si = 0; si < 8; si++) {
            float x0, x1, x2, x3;
            UNPACK2(x0, x1, acc[si][0]);
            UNPACK2(x2, x3, acc[si][1]);
            float* fr = feat + (sg * 8 + si) * F_ + ft * 4;
            fr[0] = fmaxf(x0 + b0, 0.f);
            fr[1] = fmaxf(x1 + b1, 0.f);
            fr[2] = fmaxf(x2 + b2, 0.f);
            fr[3] = fmaxf(x3 + b3, 0.f);
        }
    }
    __syncthreads();

    for (int idx = tid; idx < 64 * T_; idx += 256) {
        int s = idx / T_, t = idx - s * T_;
        float d = __ldg(&fc_b[t]);
        const float* fv = feat + s * F_;
        const float* fw = fcwT + t;
        #pragma unroll 10
        for (int f = 0; f < F_; f++) d += fv[f] * fw[f * 52];
        g_em[(b * S_ + (s0 + s)) * T_ + t] = d;
    }
}

// ---------------------------------------------------------------------------
// Kernel 2: CRF, single warp per batch, linear domain, shuffle-broadcast matvec.
// Thread t (<25) owns states j0=2t, j1=2t+1 (alpha packed f32x2).
// Step: a_j <- (sum_i p_i E[i][j]) * exp(em_s[j]); renorm every 8 steps.
// Emissions prefetched one 8-step group ahead. grid = 32, block = 32.
// Last block reduces g_part into out (deterministic order) and resets g_cnt.
// ---------------------------------------------------------------------------
__global__ __launch_bounds__(32) void k_crf(
    const int* __restrict__ tags,
    const float* __restrict__ start_trans,
    const float* __restrict__ end_trans,
    const float* __restrict__ trans,
    float* __restrict__ out)
{
    const int tid  = threadIdx.x;
    const int b    = blockIdx.x;
    const int base = b * S_;
    const bool act = (tid < 25);
    const int j0 = 2 * tid, j1 = 2 * tid + 1;

    // E columns in registers: Ej[i] = (exp(trans[2i][j]), exp(trans[2i+1][j]))
    uint64_t Ej0[25], Ej1[25];
    if (act) {
        #pragma unroll
        for (int i = 0; i < 25; i++) {
            float e00 = __expf(__ldg(&trans[(2 * i)     * T_ + j0]));
            float e01 = __expf(__ldg(&trans[(2 * i + 1) * T_ + j0]));
            float e10 = __expf(__ldg(&trans[(2 * i)     * T_ + j1]));
            float e11 = __expf(__ldg(&trans[(2 * i + 1) * T_ + j1]));
            PACK2(Ej0[i], e00, e01);
            PACK2(Ej1[i], e10, e11);
        }
    } else {
        #pragma unroll
        for (int i = 0; i < 25; i++) { Ej0[i] = 0ull; Ej1[i] = 0ull; }
    }

    // --- numerator: gold path score ---
    const int* tg = tags + base;
    float local = 0.f;
    for (int s = tid; s < S_; s += 32) {
        int t = tg[s];
        local += __ldg(&g_em[(base + s) * T_ + t]);
        if (s < S_ - 1) local += __ldg(&trans[t * T_ + tg[s + 1]]);
    }
    #pragma unroll
    for (int o = 16; o; o >>= 1) local += __shfl_xor_sync(0xffffffffu, local, o);
    float s_num = local + start_trans[tg[0]] + end_trans[tg[S_ - 1]];

    // --- init alpha (log -> linear with offset) ---
    float al0 = -3.0e38f, al1 = -3.0e38f;
    if (act) {
        float2 e0 = *(const float2*)&g_em[base * T_ + j0];
        al0 = __ldg(&start_trans[j0]) + e0.x;
        al1 = __ldg(&start_trans[j1]) + e0.y;
    }
    float mv = fmaxf(al0, al1);
    #pragma unroll
    for (int o = 16; o; o >>= 1) mv = fmaxf(mv, __shfl_xor_sync(0xffffffffu, mv, o));
    float off = mv;
    uint64_t apk = 0ull;
    if (act) { PACK2(apk, __expf(al0 - mv), __expf(al1 - mv)); }

    // --- forward scan: 63 full groups of 8 (s=1..504) + 1 partial of 7 ---
    float2 bufA[8], bufB[8];
    #pragma unroll
    for (int k = 0; k < 8; k++) { bufA[k] = make_float2(0.f, 0.f); bufB[k] = make_float2(0.f, 0.f); }
    if (act) {
        #pragma unroll
        for (int k = 0; k < 8; k++)
            bufA[k] = __ldg((const float2*)&g_em[(base + 1 + k) * T_ + j0]);
    }

    for (int g = 0; g < 64; g++) {
        // prefetch next group (consumed ~1000 cycles from now)
        if (g < 63 && act) {
            int sn = 8 * g + 9;
            #pragma unroll
            for (int k = 0; k < 8; k++)
                if (sn + k < S_) bufB[k] = __ldg((const float2*)&g_em[(base + sn + k) * T_ + j0]);
        }
        // exps for this group (off critical path of first steps)
        uint64_t eem[8];
        #pragma unroll
        for (int k = 0; k < 8; k++) {
            float e0 = __expf(bufA[k].x), e1 = __expf(bufA[k].y);
            PACK2(eem[k], e0, e1);
        }
        const int nst = (g < 63) ? 8 : 7;
        #pragma unroll
        for (int k = 0; k < 8; k++) {
            if (k >= nst) break;
            uint64_t d00 = 0ull, d01 = 0ull, d10 = 0ull, d11 = 0ull;
            #pragma unroll
            for (int i = 0; i < 25; i++) {
                uint64_t pv = __shfl_sync(0xffffffffu, apk, i);
                if (i & 1) { FMA2(d01, pv, Ej0[i]); FMA2(d11, pv, Ej1[i]); }
                else       { FMA2(d00, pv, Ej0[i]); FMA2(d10, pv, Ej1[i]); }
            }
            float l, h;
            UNPACK2(l, h, d00); float sm0 = l + h;
            UNPACK2(l, h, d01); sm0 += l + h;
            UNPACK2(l, h, d10); float sm1 = l + h;
            UNPACK2(l, h, d11); sm1 += l + h;
            uint64_t sp;
            PACK2(sp, sm0, sm1);
            MUL2(apk, sp, eem[k]);
            if (!act) apk = 0ull;
        }
        if (g < 63) {
            float a0, a1;
            UNPACK2(a0, a1, apk);
            float m = fmaxf(a0, a1);
            #pragma unroll
            for (int o = 16; o; o >>= 1) m = fmaxf(m, __shfl_xor_sync(0xffffffffu, m, o));
            float inv = 1.0f / m;
            off += __logf(m);
            uint64_t ip; PACK2(ip, inv, inv);
            MUL2(apk, apk, ip);
        }
        #pragma unroll
        for (int k = 0; k < 8; k++) bufA[k] = bufB[k];
    }

    // --- log_z = off + log(sum_j a_j * exp(end_trans_j)) ---
    float av = 0.f;
    if (act) {
        float a0, a1; UNPACK2(a0, a1, apk);
        av = a0 * __expf(__ldg(&end_trans[j0])) + a1 * __expf(__ldg(&end_trans[j1]));
    }
    #pragma unroll
    for (int o = 16; o; o >>= 1) av += __shfl_xor_sync(0xffffffffu, av, o);
    if (tid == 0) g_part[b] = (off + logf(av)) - s_num;

    // --- last block reduces g_part -> out (deterministic), resets counter ---
    unsigned isl = 0;
    if (tid == 0) {
        __threadfence();
        unsigned prev = atomicAdd(&g_cnt, 1u);
        isl = (prev == B_ - 1) ? 1u : 0u;
    }
    isl = __shfl_sync(0xffffffffu, isl, 0);
    if (isl) {
        __threadfence();
        float v = g_part[tid];
        #pragma unroll
        for (int o = 16; o; o >>= 1) v += __shfl_xor_sync(0xffffffffu, v, o);
        if (tid == 0) { out[0] = v; g_cnt = 0u; }
    }
}

extern "C" void kernel_launch(void* const* d_in, const int* in_sizes, int n_in,
                              void* d_out, int out_size)
{
    const int*   x           = (const int*)  d_in[0];
    const int*   tags        = (const int*)  d_in[1];
    const float* emb         = (const float*)d_in[2];
    const float* conv_w      = (const float*)d_in[3];
    const float* conv_b      = (const float*)d_in[4];
    const float* fc_w        = (const float*)d_in[5];
    const float* fc_b        = (const float*)d_in[6];
    const float* start_trans = (const float*)d_in[7];
    const float* end_trans   = (const float*)d_in[8];
    const float* trans       = (const float*)d_in[9];
    float* out = (float*)d_out;

    k_wt<<<(F_ * E_ * 3 + 255) / 256, 256>>>(conv_w);
    k_emissions<<<dim3(S_ / 64, B_), 256>>>(x, emb, conv_b, fc_w, fc_b);
    k_crf<<<B_, 32>>>(tags, start_trans, end_trans, trans, out);
}